// round 8
// baseline (speedup 1.0000x reference)
#include <cuda_runtime.h>
#include <cstdint>
#include <math.h>

#define NUM_BINS 16
#define BOUND 3.0f
#define MIN_BIN_WIDTH 0.001f
#define MIN_BIN_HEIGHT 0.001f
#define MIN_DERIVATIVE 0.001f
#define MIN_LAMBDA 0.025f
#define EPS_C 1e-6f

#define TPB 64
#define TILE 64
#define P 63                       // params per element in global
#define SP 47                      // staged params per element (w16 + h16 + d15)
#define TILE_SFLOATS (TILE * SP)   // 3008 floats = 12032 B per buffer

#define CP_ASYNC4(saddr, gptr) \
    asm volatile("cp.async.ca.shared.global [%0], [%1], 4;\n" :: "r"(saddr), "l"(gptr))
#define CP_COMMIT() asm volatile("cp.async.commit_group;\n" ::)
#define CP_WAIT1()  asm volatile("cp.async.wait_group 1;\n" ::)
#define CP_WAIT0()  asm volatile("cp.async.wait_group 0;\n" ::)

__global__ __launch_bounds__(TPB) void lrs_kernel(
    const float* __restrict__ inputs,
    const float* __restrict__ params,
    float* __restrict__ out,
    int n, int ntiles)
{
    __shared__ float sm[2][TILE_SFLOATS];   // 2 * 12032 B = 24064 B -> 9 CTAs/SM

    const int tid = threadIdx.x;
    const int G = gridDim.x;

    // stage first SP floats of each of TILE rows into buffer b (linear smem layout)
    auto stage = [&](int t, int b) {
        const int base = t * TILE;
        uint32_t sbase = (uint32_t)__cvta_generic_to_shared(&sm[b][0]);
        const float* gsrc = params + (size_t)base * P;
        if (base + TILE <= n) {
            #pragma unroll
            for (int k = 0; k < SP; k++) {               // 47 iters, MLP high
                int i = k * TPB + tid;                   // i in [0, 3008)
                int e = i / SP;                          // element within tile
                int f = i - e * SP;                      // param index 0..46
                CP_ASYNC4(sbase + (uint32_t)i * 4, gsrc + (size_t)e * P + f);
            }
        } else {
            int rem = n - base;
            for (int i = tid; i < rem * SP; i += TPB) {
                int e = i / SP, f = i - e * SP;
                CP_ASYNC4(sbase + (uint32_t)i * 4, gsrc + (size_t)e * P + f);
            }
        }
    };

    int t0 = blockIdx.x;
    if (t0 < ntiles) stage(t0, 0);
    CP_COMMIT();

    int j = 0;
    for (int t = t0; t < ntiles; t += G, j++) {
        int tn = t + G;
        if (tn < ntiles) {
            stage(tn, (j + 1) & 1);
            CP_COMMIT();
            CP_WAIT1();           // tile t's stage complete
        } else {
            CP_WAIT0();
        }
        __syncthreads();

        const int elem = t * TILE + tid;
        if (elem < n) {
            const float* mp = &sm[j & 1][tid * SP];   // stride 47 (odd): conflict-free
            const float x = __ldg(inputs + elem);

            // ========== widths softmax (register-resident, no max-sub) ==========
            float ew[NUM_BINS];
            float s = 0.0f;
            #pragma unroll
            for (int k = 0; k < NUM_BINS; k++) { ew[k] = __expf(mp[k]); s += ew[k]; }
            const float wscale = (1.0f - MIN_BIN_WIDTH * NUM_BINS) * __fdividef(1.0f, s);

            int cnt = (x >= -BOUND + EPS_C) ? 1 : 0;
            float cwL = -BOUND, cwR = BOUND;
            bool haveR = false;
            {
                float cum = 0.0f;
                #pragma unroll
                for (int k = 0; k < NUM_BINS; k++) {
                    cum += fmaf(wscale, ew[k], MIN_BIN_WIDTH);
                    float knot = (k == NUM_BINS - 1) ? BOUND : fmaf(cum, 2.0f * BOUND, -BOUND);
                    if (x >= knot + EPS_C) { cnt++; cwL = knot; }
                    else if (!haveR)       { haveR = true; cwR = knot; }
                }
            }
            const int bin = min(max(cnt - 1, 0), NUM_BINS - 1);
            const float in_w = cwR - cwL;

            // single scattered load (lam) — issue NOW, consume after long MUFU chains
            const float lamraw = __ldg(params + (size_t)elem * P + (3 * NUM_BINS - 1) + bin);

            // dL/dR raw from smem (staged; guarded indices stay within [0,47))
            const float dLraw = (bin > 0)            ? mp[(2 * NUM_BINS - 1) + bin] : 0.0f;
            const float dRraw = (bin < NUM_BINS - 1) ? mp[2 * NUM_BINS + bin]       : 0.0f;

            // ========== heights softmax ==========
            float eh[NUM_BINS];
            float sh = 0.0f;
            #pragma unroll
            for (int k = 0; k < NUM_BINS; k++) { eh[k] = __expf(mp[NUM_BINS + k]); sh += eh[k]; }
            const float hscale = (1.0f - MIN_BIN_HEIGHT * NUM_BINS) * __fdividef(1.0f, sh);

            float chL = -BOUND, chR = BOUND;
            {
                float cum = 0.0f;
                #pragma unroll
                for (int k = 0; k < NUM_BINS; k++) {
                    cum += fmaf(hscale, eh[k], MIN_BIN_HEIGHT);
                    float knot = (k == NUM_BINS - 1) ? BOUND : fmaf(cum, 2.0f * BOUND, -BOUND);
                    if (k + 1 == bin) chL = knot;
                    if (k == bin)     chR = knot;
                }
            }
            const float in_h = chR - chL;

            // ========== derivatives (2 softplus) ==========
            const float edge = 1.0f - MIN_DERIVATIVE;
            float dL, dR;
            if (bin > 0)
                dL = MIN_DERIVATIVE + fmaxf(dLraw, 0.0f) + __logf(1.0f + __expf(-fabsf(dLraw)));
            else dL = edge;
            if (bin < NUM_BINS - 1)
                dR = MIN_DERIVATIVE + fmaxf(dRraw, 0.0f) + __logf(1.0f + __expf(-fabsf(dRraw)));
            else dR = edge;

            // lambda (consumes the scattered load, ~long after issue)
            const float sig = __fdividef(1.0f, 1.0f + __expf(-lamraw));
            const float lam = fmaf(1.0f - 2.0f * MIN_LAMBDA, sig, MIN_LAMBDA);

            // ========== spline evaluation ==========
            const float r_inw = __fdividef(1.0f, in_w);
            const float r_inh = __fdividef(1.0f, in_h);
            const float wb  = sqrtf(__fdividef(dL, dR));
            const float lwb = lam * wb;
            const float wc  = (lam * dL + (wb - lwb) * dR) * in_w * r_inh;
            const float ya  = chL;
            const float yb  = in_h + chL;
            const float l1  = 1.0f - lam;
            const float yc  = __fdividef(lwb * yb + l1 * ya, l1 + lwb);

            const float theta  = (x - cwL) * r_inw;
            const bool  ind    = theta <= lam;
            const float ltheta = lam - theta;
            const float wcyc   = wc * yc;
            const float wcyctheta = wcyc * theta;
            const float wbyb   = wb * yb;
            const float numerator   = ind ? (wcyctheta + ya * ltheta)
                                          : ((wcyc - wcyctheta) - wbyb * ltheta);
            const float wctheta = wc * theta;
            const float denominator = ind ? (wctheta + ltheta)
                                          : ((wc - wctheta) - wb * ltheta);
            const float rden   = __fdividef(1.0f, denominator);
            const float result = numerator * rden;

            const float dnum = wc * (ind ? (lam * (yc - ya)) : ((wb - lwb) * (yb - yc))) * r_inw;
            const float lad  = __logf(dnum * rden * rden);

            const bool outside = (x < -BOUND) || (x > BOUND);
            out[elem]     = outside ? x : result;
            out[n + elem] = outside ? 0.0f : lad;
        }
        __syncthreads();          // reads of buf[j&1] done before restage
    }
}

extern "C" void kernel_launch(void* const* d_in, const int* in_sizes, int n_in,
                              void* d_out, int out_size) {
    const float* inputs = (const float*)d_in[0];
    const float* params = (const float*)d_in[1];
    float* out = (float*)d_out;
    int n = in_sizes[0];
    int ntiles = (n + TILE - 1) / TILE;
    int grid = 152 * 9;               // persistent: 9 CTAs/SM (24.1 KB smem each)
    if (grid > ntiles) grid = ntiles;
    lrs_kernel<<<grid, TPB>>>(inputs, params, out, n, ntiles);
}

// round 10
// speedup vs baseline: 1.4238x; 1.4238x over previous
#include <cuda_runtime.h>
#include <cstdint>
#include <math.h>

#define NUM_BINS 16
#define BOUND 3.0f
#define MIN_BIN_WIDTH 0.001f
#define MIN_BIN_HEIGHT 0.001f
#define MIN_DERIVATIVE 0.001f
#define MIN_LAMBDA 0.025f
#define EPS_C 1e-6f

#define TPB 64
#define TILE 64
#define P 63
// compact staged layout: 4-row groups; 50 kept 16B-vectors/group, stride padded to 816B
#define GROUP_STRIDE_B 816
#define GROUP_STRIDE_W 204        // words; 204 mod 32 = 12 -> conflict-free with 51-word rows
#define ROW_OFF_W 51              // 51 mod 32 = 19
#define BUF_WORDS (16 * GROUP_STRIDE_W)   // 3264 words = 13056 B per buffer

#define CP_ASYNC16(saddr, gptr) \
    asm volatile("cp.async.cg.shared.global [%0], [%1], 16;\n" :: "r"(saddr), "l"(gptr))
#define CP_COMMIT() asm volatile("cp.async.commit_group;\n" ::)
#define CP_WAIT1()  asm volatile("cp.async.wait_group 1;\n" ::)
#define CP_WAIT0()  asm volatile("cp.async.wait_group 0;\n" ::)

__global__ __launch_bounds__(TPB, 8) void lrs_kernel(
    const float* __restrict__ inputs,
    const float* __restrict__ params,
    float* __restrict__ out,
    int n, int ntiles)
{
    __shared__ float sm[2][BUF_WORDS];   // 2 * 13056 B = 26112 B -> 8 CTAs/SM

    const int tid = threadIdx.x;
    const int G = gridDim.x;
    const uint32_t sm_u32 = (uint32_t)__cvta_generic_to_shared(&sm[0][0]);

    // stage kept vectors of tile t into buffer b (skips lam-only vectors)
    auto stage = [&](int t, int b) {
        const char* gbase = (const char*)(params + (size_t)(t * TILE) * P);
        const uint32_t sbase = sm_u32 + (uint32_t)b * (BUF_WORDS * 4);
        // 800 kept vectors per tile = 12 full iters + tail 32
        #pragma unroll
        for (int it = 0; it < 12; it++) {
            int vI = it * TPB + tid;
            int g = vI / 50;                 // group (4 rows)
            int s = vI - g * 50;             // kept-slot within group
            int v = s + 3 * ((s >= 12) + (s >= 25) + (s >= 38));  // global vec in group
            CP_ASYNC16(sbase + (uint32_t)(g * GROUP_STRIDE_B + s * 16),
                       gbase + ((size_t)g * 1008 + (size_t)v * 16));
        }
        {
            int vI = 12 * TPB + tid;
            if (vI < 800) {
                int g = vI / 50;
                int s = vI - g * 50;
                int v = s + 3 * ((s >= 12) + (s >= 25) + (s >= 38));
                CP_ASYNC16(sbase + (uint32_t)(g * GROUP_STRIDE_B + s * 16),
                           gbase + ((size_t)g * 1008 + (size_t)v * 16));
            }
        }
    };

    int t0 = blockIdx.x;
    if (t0 < ntiles && (t0 + 1) * TILE <= n) stage(t0, 0);
    CP_COMMIT();

    int j = 0;
    for (int t = t0; t < ntiles; t += G, j++) {
        int tn = t + G;
        bool full = (t + 1) * TILE <= n;
        if (tn < ntiles && (tn + 1) * TILE <= n) {
            stage(tn, (j + 1) & 1);
            CP_COMMIT();
            CP_WAIT1();
        } else {
            CP_WAIT0();
        }
        __syncthreads();

        const int elem = t * TILE + tid;
        if (elem < n) {
            // compact per-thread base: group = tid/4, row-in-group = tid%4
            const float* mp = &sm[j & 1][(tid >> 2) * GROUP_STRIDE_W + (tid & 3) * ROW_OFF_W];
            const float* grow = params + (size_t)elem * P;   // fallback + lam source
            const float x = __ldg(inputs + elem);

            // ragged-tile fallback (not hit for n = multiple of TILE)
            float wraw[NUM_BINS];
            if (full) {
                #pragma unroll
                for (int k = 0; k < NUM_BINS; k++) wraw[k] = mp[k];
            } else {
                #pragma unroll
                for (int k = 0; k < NUM_BINS; k++) wraw[k] = __ldg(grow + k);
            }

            // ========== widths softmax (register-resident, no max-sub) ==========
            float ew[NUM_BINS];
            float s = 0.0f;
            #pragma unroll
            for (int k = 0; k < NUM_BINS; k++) { ew[k] = __expf(wraw[k]); s += ew[k]; }
            const float wscale = (1.0f - MIN_BIN_WIDTH * NUM_BINS) * __fdividef(1.0f, s);

            int cnt = (x >= -BOUND + EPS_C) ? 1 : 0;
            float cwL = -BOUND, cwR = BOUND;
            bool haveR = false;
            {
                float cum = 0.0f;
                #pragma unroll
                for (int k = 0; k < NUM_BINS; k++) {
                    cum += fmaf(wscale, ew[k], MIN_BIN_WIDTH);
                    float knot = (k == NUM_BINS - 1) ? BOUND : fmaf(cum, 2.0f * BOUND, -BOUND);
                    if (x >= knot + EPS_C) { cnt++; cwL = knot; }
                    else if (!haveR)       { haveR = true; cwR = knot; }
                }
            }
            const int bin = min(max(cnt - 1, 0), NUM_BINS - 1);
            const float in_w = cwR - cwL;

            // single scattered load (lam) — issue now, consume after long MUFU chains
            const float lamraw = __ldg(grow + (3 * NUM_BINS - 1) + bin);

            // dL/dR raw (staged; indices 32..46 stay inside compact range)
            const float dLraw = (bin > 0)
                ? (full ? mp[(2 * NUM_BINS - 1) + bin] : __ldg(grow + (2 * NUM_BINS - 1) + bin))
                : 0.0f;
            const float dRraw = (bin < NUM_BINS - 1)
                ? (full ? mp[2 * NUM_BINS + bin] : __ldg(grow + 2 * NUM_BINS + bin))
                : 0.0f;

            // ========== heights softmax ==========
            float eh[NUM_BINS];
            float sh = 0.0f;
            #pragma unroll
            for (int k = 0; k < NUM_BINS; k++) {
                float hr = full ? mp[NUM_BINS + k] : __ldg(grow + NUM_BINS + k);
                eh[k] = __expf(hr);
                sh += eh[k];
            }
            const float hscale = (1.0f - MIN_BIN_HEIGHT * NUM_BINS) * __fdividef(1.0f, sh);

            float chL = -BOUND, chR = BOUND;
            {
                float cum = 0.0f;
                #pragma unroll
                for (int k = 0; k < NUM_BINS; k++) {
                    cum += fmaf(hscale, eh[k], MIN_BIN_HEIGHT);
                    float knot = (k == NUM_BINS - 1) ? BOUND : fmaf(cum, 2.0f * BOUND, -BOUND);
                    if (k + 1 == bin) chL = knot;
                    if (k == bin)     chR = knot;
                }
            }
            const float in_h = chR - chL;

            // ========== derivatives (2 softplus) ==========
            const float edge = 1.0f - MIN_DERIVATIVE;
            float dL, dR;
            if (bin > 0)
                dL = MIN_DERIVATIVE + fmaxf(dLraw, 0.0f) + __logf(1.0f + __expf(-fabsf(dLraw)));
            else dL = edge;
            if (bin < NUM_BINS - 1)
                dR = MIN_DERIVATIVE + fmaxf(dRraw, 0.0f) + __logf(1.0f + __expf(-fabsf(dRraw)));
            else dR = edge;

            // lambda (consumes scattered load late)
            const float sig = __fdividef(1.0f, 1.0f + __expf(-lamraw));
            const float lam = fmaf(1.0f - 2.0f * MIN_LAMBDA, sig, MIN_LAMBDA);

            // ========== spline evaluation ==========
            const float r_inw = __fdividef(1.0f, in_w);
            const float r_inh = __fdividef(1.0f, in_h);
            const float wb  = sqrtf(__fdividef(dL, dR));
            const float lwb = lam * wb;
            const float wc  = (lam * dL + (wb - lwb) * dR) * in_w * r_inh;
            const float ya  = chL;
            const float yb  = in_h + chL;
            const float l1  = 1.0f - lam;
            const float yc  = __fdividef(lwb * yb + l1 * ya, l1 + lwb);

            const float theta  = (x - cwL) * r_inw;
            const bool  ind    = theta <= lam;
            const float ltheta = lam - theta;
            const float wcyc   = wc * yc;
            const float wcyctheta = wcyc * theta;
            const float wbyb   = wb * yb;
            const float numerator   = ind ? (wcyctheta + ya * ltheta)
                                          : ((wcyc - wcyctheta) - wbyb * ltheta);
            const float wctheta = wc * theta;
            const float denominator = ind ? (wctheta + ltheta)
                                          : ((wc - wctheta) - wb * ltheta);
            const float rden   = __fdividef(1.0f, denominator);
            const float result = numerator * rden;

            const float dnum = wc * (ind ? (lam * (yc - ya)) : ((wb - lwb) * (yb - yc))) * r_inw;
            const float lad  = __logf(dnum * rden * rden);

            const bool outside = (x < -BOUND) || (x > BOUND);
            out[elem]     = outside ? x : result;
            out[n + elem] = outside ? 0.0f : lad;
        }
        __syncthreads();          // reads of buf[j&1] done before restage
    }
}

extern "C" void kernel_launch(void* const* d_in, const int* in_sizes, int n_in,
                              void* d_out, int out_size) {
    const float* inputs = (const float*)d_in[0];
    const float* params = (const float*)d_in[1];
    float* out = (float*)d_out;
    int n = in_sizes[0];
    int ntiles = (n + TILE - 1) / TILE;
    int grid = 152 * 8;               // persistent: 8 CTAs/SM (26.1 KB smem each)
    if (grid > ntiles) grid = ntiles;
    lrs_kernel<<<grid, TPB>>>(inputs, params, out, n, ntiles);
}